// round 7
// baseline (speedup 1.0000x reference)
#include <cuda_runtime.h>
#include <cstdint>

#define CTC_V  128
#define NEG2   (-1.0e30f)
#define KS     8                  // steps per barrier block (== halo depth)
#define NWRP   11
#define NTHR   (NWRP * 32)        // 352
#define TMAX   1024
#define PPAD   258
#define PSH    268                // shared alpha slots (11*24=264, padded)

__device__ float2 g_final[64 * PPAD];

__device__ __forceinline__ float ex2(float x) {
    float y; asm("ex2.approx.ftz.f32 %0, %1;" : "=f"(y) : "f"(x)); return y;
}
__device__ __forceinline__ float lg2(float x) {
    float y; asm("lg2.approx.ftz.f32 %0, %1;" : "=f"(y) : "f"(x)); return y;
}

// ---------------------------------------------------------------------------
// Fused kernel: phase 1 computes lse2[t] (log2-sum-exp2 of acts*log2e) for
// this batch; phase 2 runs the alpha recursion reading raw acts + lse2.
// One CTA per batch. 1 pair/thread (pair p = blank state 2p + label state
// 2p+1), halo-8 lanes, 8 steps per barrier.
// ---------------------------------------------------------------------------
__global__ __launch_bounds__(NTHR, 1) void ctc_fused_k(
    const float* __restrict__ acts, const int* __restrict__ labels,
    const int* __restrict__ act_lens, const int* __restrict__ label_lens,
    int T, int B, int L)
{
    __shared__ float  lse2[TMAX];
    __shared__ __align__(8) float2 shA[2][PSH];

    const int V = CTC_V;
    const int b = blockIdx.x;
    const int P = L + 1;
    const int tid = threadIdx.x, lane = tid & 31, w = tid >> 5;
    const float L2E = 1.4426950408889634f;

    int Tlen = act_lens[b];
    if (Tlen > T) Tlen = T;
    if (Tlen < 1) Tlen = 1;
    const int Lb = label_lens[b];
    (void)Lb;

    // ---------------- Phase 1: lse2[t] for all t ----------------
    // 4 rows per warp; 8 lanes per row, each lane handles 16 of 128 values.
    {
        int sub = lane >> 3, sl = lane & 7;
        for (int t0 = w * 4; t0 < T; t0 += NWRP * 4) {
            int t = t0 + sub;
            if (t < T) {
                const float4* rp = reinterpret_cast<const float4*>(acts)
                                   + ((size_t)t * B + b) * 32 + sl * 4;
                float4 v0 = __ldg(rp), v1 = __ldg(rp + 1);
                float4 v2 = __ldg(rp + 2), v3 = __ldg(rp + 3);
                float x[16] = {v0.x,v0.y,v0.z,v0.w, v1.x,v1.y,v1.z,v1.w,
                               v2.x,v2.y,v2.z,v2.w, v3.x,v3.y,v3.z,v3.w};
                float m = x[0] * L2E;
#pragma unroll
                for (int i = 1; i < 16; ++i) m = fmaxf(m, x[i] * L2E);
#pragma unroll
                for (int o = 1; o < 8; o <<= 1) m = fmaxf(m, __shfl_xor_sync(0xffffffffu, m, o));
                float s = 0.0f;
#pragma unroll
                for (int i = 0; i < 16; ++i) s += ex2(fmaf(x[i], L2E, -m));
#pragma unroll
                for (int o = 1; o < 8; o <<= 1) s += __shfl_xor_sync(0xffffffffu, s, o);
                if (sl == 0) lse2[t] = m + lg2(s);
            }
        }
    }

    // ---------------- per-thread pair setup ----------------
    const int p = w * 24 + lane - KS;          // pair index (halo lanes: p of left nbr / <0)
    const bool in0 = ((unsigned)p < (unsigned)P);   // blank state 2p exists
    const bool in1 = ((unsigned)p < (unsigned)L);   // label state 2p+1 exists
    const int  lab   = in1 ? labels[b * L + p] : 0;
    const bool allow = in1 && (p >= 1) && (lab != labels[b * L + p - 1]);
    const bool useful = (lane >= KS) && in0;

    const float* __restrict__ pb = acts + (size_t)b * V;        // blank (v=0)
    const float* __restrict__ pl = acts + (size_t)b * V + lab;  // label stream
    const size_t rstr = (size_t)B * V;

    __syncthreads();   // lse2 ready

    // ---------------- t = 0 init ----------------
    if (useful) {
        float c0 = NEG2, c1 = NEG2;
        if (p == 0) {
            float l0 = lse2[0];
            c0 = fmaf(__ldg(pb), L2E, -l0);
            c1 = in1 ? fmaf(__ldg(pl), L2E, -l0) : NEG2;
        }
        shA[0][p] = make_float2(c0, c1);
    }

    // emits for block 0 (t = 1..KS)
    float eb[KS], el[KS];
#pragma unroll
    for (int j = 0; j < KS; ++j) {
        int t = 1 + j; bool ok = (t < Tlen);
        float ls = lse2[ok ? t : 0];
        eb[j] = ok ? fmaf(__ldg(pb + (size_t)t * rstr), L2E, -ls) : 0.0f;
        el[j] = ok ? fmaf(__ldg(pl + (size_t)t * rstr), L2E, -ls) : 0.0f;
    }
    __syncthreads();   // shA[0] ready

    const int NB = (Tlen - 1 + KS - 1) / KS;
    float c0 = NEG2, c1 = NEG2;

    for (int blk = 0; blk < NB; ++blk) {
        // load state at time blk*KS
        {
            int pq = p < 0 ? 0 : p;
            float2 v = shA[blk & 1][pq];
            bool ok = (p >= 0) && in0;
            c0 = ok ? v.x : NEG2;
            c1 = (ok && in1) ? v.y : NEG2;
        }
        // prefetch emits for next block
        float nb_[KS], nl_[KS];
        {
            int tb = (blk + 1) * KS + 1;
#pragma unroll
            for (int j = 0; j < KS; ++j) {
                int t = tb + j; bool ok = (t < Tlen);
                float ls = lse2[ok ? t : 0];
                nb_[j] = ok ? fmaf(__ldg(pb + (size_t)t * rstr), L2E, -ls) : 0.0f;
                nl_[j] = ok ? fmaf(__ldg(pl + (size_t)t * rstr), L2E, -ls) : 0.0f;
            }
        }

        // KS recursion steps
#pragma unroll
        for (int j = 0; j < KS; ++j) {
            int t = blk * KS + 1 + j;
            float z = __shfl_up_sync(0xffffffffu, c1, 1);   // c1 of pair p-1
            // blank: s0 = logadd2(c0, z) + eb
            float m0 = fmaxf(c0, z);
            float s0 = m0 + lg2(1.0f + ex2(fminf(c0, z) - m0)) + eb[j];
            // label: s1 = logadd3(c1, c0, allow? z) + el
            float q  = allow ? z : NEG2;
            float h  = fmaxf(c1, c0), lo = fminf(c1, c0);
            float m1 = fmaxf(h, q),  l2v = fminf(h, q);
            float s1 = m1 + lg2(1.0f + ex2(lo - m1) + ex2(l2v - m1)) + el[j];
            bool upd = (t < Tlen);
            c0 = (upd && in0) ? s0 : c0;
            c1 = (upd && in1) ? s1 : c1;
        }

        if (useful) shA[(blk + 1) & 1][p] = make_float2(c0, c1);
        __syncthreads();

#pragma unroll
        for (int j = 0; j < KS; ++j) { eb[j] = nb_[j]; el[j] = nl_[j]; }
    }

    // final alpha -> global (registers of useful lanes hold final state)
    if (useful) {
        float2 v = shA[NB & 1][p];
        g_final[(size_t)b * PPAD + p] = v;
    }
}

// ---------------------------------------------------------------------------
// Cost + deterministic sum.
// ---------------------------------------------------------------------------
__global__ void cost_k(float* out, const int* __restrict__ label_lens, int B, int L) {
    int P = L + 1;
    float sum = 0.0f;
    for (int i = threadIdx.x; i < B; i += 32) {
        int e = label_lens[i]; if (e > P - 1) e = P - 1;
        float2 f0 = g_final[(size_t)i * PPAD + e];
        float a0 = f0.x;
        float a1 = (e >= 1) ? g_final[(size_t)i * PPAD + e - 1].y : NEG2;
        float m = fmaxf(a0, a1);
        sum += -(m + lg2(ex2(a0 - m) + ex2(a1 - m))) * 0.69314718055994530942f;
    }
#pragma unroll
    for (int o = 16; o; o >>= 1) sum += __shfl_xor_sync(0xffffffffu, sum, o);
    if (threadIdx.x == 0) *out = sum;
}

// ---------------------------------------------------------------------------
extern "C" void kernel_launch(void* const* d_in, const int* in_sizes, int n_in,
                              void* d_out, int out_size)
{
    const float* acts      = (const float*)d_in[0];
    const int*   labels    = (const int*)d_in[1];
    const int*   act_lens  = (const int*)d_in[2];
    const int*   label_len = (const int*)d_in[3];

    int B = in_sizes[2];
    int L = in_sizes[1] / B;
    int V = CTC_V;
    int T = in_sizes[0] / (B * V);

    ctc_fused_k<<<B, NTHR>>>(acts, labels, act_lens, label_len, T, B, L);
    cost_k<<<1, 32>>>((float*)d_out, label_len, B, L);
}